// round 14
// baseline (speedup 1.0000x reference)
#include <cuda_runtime.h>
#include <cuda_bf16.h>
#include <math.h>
#include <stdint.h>

#define B      128
#define D      524288          // 512*32*32
#define D4     (D/4)           // 131072 float4 per row
#define NC     12
#define KT     128             // floats per row per chunk
#define NCHUNK (D/KT)          // 4096
#define NCTA2  296             // 2 CTAs per SM x 148 SMs (all co-resident)
#define K1_THREADS 512

// dynamic smem: two bf16 tiles [B][TP]
#define TP     136             // bf16 tile row pitch (128 + 8 pad)
#define TILE0  0
#define TILE1  (B * TP * 2)
#define SMEM_DYN (2 * B * TP * 2)   // 69632

// -------- device scratch --------
__device__ float g_pd[B * B];            // Gram accumulator (same-class cells used)
__device__ unsigned int g_zero_ctr;      // monotonic zero-arrive counter (init 0)

// =====================================================================
// shared prep: class-sort slots from labels (recomputed per CTA)
// fills: cstart[NC+1]; slot2sample[B] (slot -> sample idx)
// =====================================================================
__device__ __forceinline__ void prep_slots(const int* __restrict__ labels,
                                           int tid, int nthreads,
                                           int* sl, int* ccount, int* cstart,
                                           int* slot2sample) {
    if (tid < NC) ccount[tid] = 0;
    if (tid < B)  sl[tid] = labels[tid];
    __syncthreads();
    if (tid < B) atomicAdd(&ccount[sl[tid]], 1);
    __syncthreads();
    if (tid == 0) {
        int st = 0;
        for (int c = 0; c < NC; ++c) { cstart[c] = st; st += ccount[c]; }
        cstart[NC] = st;
    }
    __syncthreads();
    if (tid < B) {
        int my = sl[tid];
        int r = 0;
        for (int j = 0; j < tid; ++j) r += (sl[j] == my);
        slot2sample[cstart[my] + r] = tid;
    }
    (void)nthreads;
}

// band bounds from cstart (thread 0 only; caller syncs)
__device__ __forceinline__ void prep_bands(const int* cstart, int* b0, int* nt) {
    int wide = 0;
    int tmp[8];
    for (int s = 0; s < 8; ++s) {
        int slot = 16 * s, cls = 0;
        for (int c = 0; c < NC; ++c)
            if (slot >= cstart[c] && slot < cstart[c + 1]) cls = c;
        int nb0 = cstart[cls] & ~7;
        if (nb0 > B - 64) nb0 = B - 64;
        tmp[s] = nb0;
        int slot2 = 16 * s + 15, ce2 = B;
        for (int c = 0; c < NC; ++c)
            if (slot2 >= cstart[c] && slot2 < cstart[c + 1]) ce2 = cstart[c + 1];
        if (ce2 - tmp[s] > 64) wide = 1;
    }
    for (int s = 0; s < 8; ++s) b0[s] = wide ? 0 : tmp[s];
    *nt = wide ? 4 : 2;
}

// =====================================================================
// PTX helpers (base-ISA: ldmatrix, mma.sync)
// =====================================================================
__device__ __forceinline__ void ldsm4(uint32_t& r0, uint32_t& r1, uint32_t& r2,
                                      uint32_t& r3, uint32_t addr) {
    asm volatile("ldmatrix.sync.aligned.m8n8.x4.shared.b16 {%0,%1,%2,%3}, [%4];"
                 : "=r"(r0), "=r"(r1), "=r"(r2), "=r"(r3) : "r"(addr));
}
__device__ __forceinline__ void mma16816(float* c, uint32_t a0, uint32_t a1,
                                         uint32_t a2, uint32_t a3,
                                         uint32_t b0, uint32_t b1) {
    asm volatile(
        "mma.sync.aligned.m16n8k16.row.col.f32.bf16.bf16.f32 "
        "{%0,%1,%2,%3}, {%4,%5,%6,%7}, {%8,%9}, {%0,%1,%2,%3};"
        : "+f"(c[0]), "+f"(c[1]), "+f"(c[2]), "+f"(c[3])
        : "r"(a0), "r"(a1), "r"(a2), "r"(a3), "r"(b0), "r"(b1));
}

// =====================================================================
// k1: persistent banded bf16 mma.sync Gram. Prep + g_pd zeroing fused
// in (generation-counter arrive/spin replaces the k0 launch).
// =====================================================================
__global__ void __launch_bounds__(K1_THREADS, 2)
k1_gram(const float* __restrict__ features, const int* __restrict__ labels) {
    extern __shared__ char smem[];
    __shared__ size_t s_roff[B];
    __shared__ int s_slot2s[B];
    __shared__ int s_sl[B], s_ccount[NC], s_cstart[NC + 1];
    __shared__ int s_b0[8];
    __shared__ int s_nt;

    const int tid  = threadIdx.x;
    const int wid  = tid >> 5;
    const int lane = tid & 31;

    // ---- per-CTA prep from labels ----
    prep_slots(labels, tid, K1_THREADS, s_sl, s_ccount, s_cstart, s_slot2s);
    __syncthreads();
    if (tid < B) s_roff[tid] = (size_t)s_slot2s[tid] * D4;
    if (tid == 0) prep_bands(s_cstart, s_b0, &s_nt);

    // ---- zero own slice of g_pd, then grid arrive/spin (monotonic gen) ----
    {
        const int base = blockIdx.x * 56;
        for (int i = tid; i < 56; i += K1_THREADS) {
            int idx = base + i;
            if (idx < B * B) g_pd[idx] = 0.0f;
        }
        __threadfence();
        __syncthreads();
        if (tid == 0) {
            unsigned int gen = atomicAdd(&g_zero_ctr, 1u) / NCTA2;
            unsigned int target = (gen + 1u) * NCTA2;
            while (atomicAdd(&g_zero_ctr, 0u) < target) { }
        }
        __syncthreads();
        __threadfence();
    }

    const float4* F4 = (const float4*)features;
    const bool wide = (s_nt == 4);
    const int nseg  = wide ? 2 : 1;

    // ---- mma mapping: warp = (strip, band half) ----
    const int strip = wid >> 1;
    const int half  = wid & 1;
    const int m0    = strip * 16;
    const int wbase = s_b0[strip] + half * (wide ? 64 : 32);

    const int a_row    = m0 + (lane & 7) + ((lane >> 3) & 1) * 8;
    const int a_col8   = (lane >> 4) * 8;
    const int b_rowoff = (lane & 7) + ((lane >> 4) & 1) * 8;
    const int b_col8   = ((lane >> 3) & 1) * 8;

    const int gid = lane >> 2;
    const int tig = lane & 3;
    const int r0 = m0 + gid, r1 = m0 + gid + 8;

    float acc[2][8];
    #pragma unroll
    for (int t = 0; t < 2; ++t)
        #pragma unroll
        for (int q = 0; q < 8; ++q) acc[t][q] = 0.0f;

    auto flush = [&](int base_n) {
        #pragma unroll
        for (int nt = 0; nt < 2; ++nt) {
            const int base = base_n + nt * 16;
            const int cA = base + tig * 2;
            const int cC = base + 8 + tig * 2;
            atomicAdd(&g_pd[r0 * B + cA],     acc[nt][0]);
            atomicAdd(&g_pd[r0 * B + cA + 1], acc[nt][1]);
            atomicAdd(&g_pd[r1 * B + cA],     acc[nt][2]);
            atomicAdd(&g_pd[r1 * B + cA + 1], acc[nt][3]);
            atomicAdd(&g_pd[r0 * B + cC],     acc[nt][4]);
            atomicAdd(&g_pd[r0 * B + cC + 1], acc[nt][5]);
            atomicAdd(&g_pd[r1 * B + cC],     acc[nt][6]);
            atomicAdd(&g_pd[r1 * B + cC + 1], acc[nt][7]);
        }
    };

    // ---- preload first chunk (8 rows/warp, float4 col = lane) ----
    float4 buf[8];
    {
        const size_t base4 = (size_t)blockIdx.x * (KT / 4) + lane;
        #pragma unroll
        for (int k = 0; k < 8; ++k)
            buf[k] = F4[s_roff[wid + k * 16] + base4];
    }

    int it = 0;
    for (int c = blockIdx.x; c < NCHUNK; c += NCTA2, ++it) {
        char* tilep = smem + ((it & 1) ? TILE1 : TILE0);
        const uint32_t tile_sh = (uint32_t)__cvta_generic_to_shared(tilep);

        // convert current buf -> STS bf16 tile
        #pragma unroll
        for (int k = 0; k < 8; ++k) {
            const int row = wid + k * 16;
            __nv_bfloat162 h0 = __float22bfloat162_rn(make_float2(buf[k].x, buf[k].y));
            __nv_bfloat162 h1 = __float22bfloat162_rn(make_float2(buf[k].z, buf[k].w));
            uint2 v;
            v.x = *(uint32_t*)&h0;
            v.y = *(uint32_t*)&h1;
            *(uint2*)(tilep + row * (TP * 2) + lane * 8) = v;
        }

        // issue NEXT chunk's LDGs (latency hidden under HMMA)
        {
            const int cn = c + NCTA2;
            if (cn < NCHUNK) {
                const size_t base4 = (size_t)cn * (KT / 4) + lane;
                #pragma unroll
                for (int k = 0; k < 8; ++k)
                    buf[k] = F4[s_roff[wid + k * 16] + base4];
            }
        }

        __syncthreads();

        // banded HMMA (1 segment) / wide fallback (2 segments)
        for (int seg = 0; seg < nseg; ++seg) {
            const int seg_base = wbase + seg * 32;
            #pragma unroll
            for (int ks = 0; ks < 8; ++ks) {
                const int k0c = ks * 16;
                uint32_t a0, a1, a2, a3;
                ldsm4(a0, a1, a2, a3,
                      tile_sh + (uint32_t)(a_row * TP + k0c + a_col8) * 2);
                #pragma unroll
                for (int nt = 0; nt < 2; ++nt) {
                    const int n0 = seg_base + nt * 16;
                    uint32_t b0, b1, b2, b3;
                    ldsm4(b0, b1, b2, b3,
                          tile_sh + (uint32_t)((n0 + b_rowoff) * TP + k0c + b_col8) * 2);
                    mma16816(&acc[nt][0], a0, a1, a2, a3, b0, b1);
                    mma16816(&acc[nt][4], a0, a1, a2, a3, b2, b3);
                }
            }
            if (wide) {
                flush(seg_base);
                #pragma unroll
                for (int t = 0; t < 2; ++t)
                    #pragma unroll
                    for (int q = 0; q < 8; ++q) acc[t][q] = 0.0f;
            }
        }
    }

    if (!wide) flush(wbase);
}

// =====================================================================
// k3: per-block prep + weights + weighted class scatter-sum
// =====================================================================
#define PF 8
__global__ void __launch_bounds__(256) k3_scatter(const float* __restrict__ features,
                                                  const int* __restrict__ labels,
                                                  float* __restrict__ out) {
    __shared__ int   s_sl[B], s_ccount[NC], s_cstart[NC + 1];
    __shared__ int   sm[B];         // slot -> sample
    __shared__ float sw[B];
    __shared__ float sdiag[B];
    __shared__ float ssum;
    int t = threadIdx.x;

    prep_slots(labels, t, 256, s_sl, s_ccount, s_cstart, sm);
    __syncthreads();
    if (t < B) sdiag[t] = g_pd[t * B + t];
    __syncthreads();

    // weights (slot t's class bounds via its sample's label)
    if (t < B) {
        int my = s_sl[sm[t]];
        int st = s_cstart[my], en = s_cstart[my + 1];
        float dsum = 0.0f;
        for (int b = st; b < en; ++b) {
            if (b == t) continue;
            float d2 = sdiag[t] + sdiag[b] - 2.0f * g_pd[t * B + b];
            dsum += (d2 > 0.0f) ? sqrtf(d2) : 0.0f;
        }
        sw[t] = 1.0f / (sqrtf(dsum * dsum + 25.0f) + 1e-12f);
    }
    __syncthreads();
    if (t == 0) {
        float S = 0.0f;
        for (int i = 0; i < B; ++i) S += sw[i];
        ssum = S + 1e-12f;
    }
    __syncthreads();
    if (t < B) sw[t] = sw[t] / ssum;
    __syncthreads();

    // weighted scatter-sum, rolling slot pass, PF-deep prefetch
    const size_t t4 = (size_t)blockIdx.x * 256 + t;
    const float4* F4 = (const float4*)features;
    float4* O4 = (float4*)out;

    float4 buf[PF];
    #pragma unroll
    for (int k = 0; k < PF; ++k)
        buf[k] = F4[(size_t)sm[k] * D4 + t4];

    int c = 0;
    int nb = s_cstart[1];
    float4 acc = make_float4(0.f, 0.f, 0.f, 0.f);

    for (int s0 = 0; s0 < B; s0 += PF) {
        #pragma unroll
        for (int k = 0; k < PF; ++k) {
            int s = s0 + k;
            while (s == nb && c < NC) {
                O4[(size_t)c * D4 + t4] = acc;
                acc = make_float4(0.f, 0.f, 0.f, 0.f);
                ++c;
                nb = s_cstart[c + 1];
            }
            float4 v = buf[k];
            float w = sw[s];
            acc.x += w * v.x; acc.y += w * v.y;
            acc.z += w * v.z; acc.w += w * v.w;
            int sp = s + PF;
            if (sp < B) buf[k] = F4[(size_t)sm[sp] * D4 + t4];
        }
    }
    while (c < NC) {
        O4[(size_t)c * D4 + t4] = acc;
        acc = make_float4(0.f, 0.f, 0.f, 0.f);
        ++c;
    }
}

// =====================================================================
extern "C" void kernel_launch(void* const* d_in, const int* in_sizes, int n_in,
                              void* d_out, int out_size) {
    const float* features;
    const int*   labels;
    if (in_sizes[0] == B) {
        labels   = (const int*)d_in[0];
        features = (const float*)d_in[1];
    } else {
        features = (const float*)d_in[0];
        labels   = (const int*)d_in[1];
    }
    float* out = (float*)d_out;

    (void)cudaFuncSetAttribute((const void*)k1_gram,
                               cudaFuncAttributeMaxDynamicSharedMemorySize,
                               SMEM_DYN);

    k1_gram<<<NCTA2, K1_THREADS, SMEM_DYN>>>(features, labels);
    k3_scatter<<<D4 / 256, 256>>>(features, labels, out);
}

// round 15
// speedup vs baseline: 1.0029x; 1.0029x over previous
#include <cuda_runtime.h>
#include <cuda_bf16.h>
#include <math.h>
#include <stdint.h>

#define B      128
#define D      524288          // 512*32*32
#define D4     (D/4)           // 131072 float4 per row
#define NC     12
#define KT     128             // floats per row per chunk
#define NCHUNK (D/KT)          // 4096
#define NCTA2  296             // 2 CTAs per SM x 148 SMs (all co-resident)
#define K1_THREADS 512

// dynamic smem: two bf16 tiles [B][TP]
#define TP     136             // bf16 tile row pitch (128 + 8 pad)
#define TILE0  0
#define TILE1  (B * TP * 2)
#define SMEM_DYN (2 * B * TP * 2)   // 69632

// -------- device scratch --------
__device__ float g_pd[B * B];            // Gram accumulator (same-class cells used)
__device__ unsigned int g_zero_ctr;      // monotonic zero-arrive counter (init 0)
__device__ int g_members[B];             // slot -> sample (published by k1 CTA0)
__device__ int g_start[NC + 1];
__device__ int g_cs[B];
__device__ int g_ce[B];

// =====================================================================
// shared prep: class-sort slots from labels (recomputed per CTA in k1)
// =====================================================================
__device__ __forceinline__ void prep_slots(const int* __restrict__ labels,
                                           int tid,
                                           int* sl, int* ccount, int* cstart,
                                           int* slot2sample) {
    if (tid < NC) ccount[tid] = 0;
    if (tid < B)  sl[tid] = labels[tid];
    __syncthreads();
    if (tid < B) atomicAdd(&ccount[sl[tid]], 1);
    __syncthreads();
    if (tid == 0) {
        int st = 0;
        for (int c = 0; c < NC; ++c) { cstart[c] = st; st += ccount[c]; }
        cstart[NC] = st;
    }
    __syncthreads();
    if (tid < B) {
        int my = sl[tid];
        int r = 0;
        for (int j = 0; j < tid; ++j) r += (sl[j] == my);
        slot2sample[cstart[my] + r] = tid;
    }
}

// band bounds from cstart (thread 0 only; caller syncs)
__device__ __forceinline__ void prep_bands(const int* cstart, int* b0, int* nt) {
    int wide = 0;
    int tmp[8];
    for (int s = 0; s < 8; ++s) {
        int slot = 16 * s, cls = 0;
        for (int c = 0; c < NC; ++c)
            if (slot >= cstart[c] && slot < cstart[c + 1]) cls = c;
        int nb0 = cstart[cls] & ~7;
        if (nb0 > B - 64) nb0 = B - 64;
        tmp[s] = nb0;
        int slot2 = 16 * s + 15, ce2 = B;
        for (int c = 0; c < NC; ++c)
            if (slot2 >= cstart[c] && slot2 < cstart[c + 1]) ce2 = cstart[c + 1];
        if (ce2 - tmp[s] > 64) wide = 1;
    }
    for (int s = 0; s < 8; ++s) b0[s] = wide ? 0 : tmp[s];
    *nt = wide ? 4 : 2;
}

// =====================================================================
// PTX helpers (base-ISA: ldmatrix, mma.sync)
// =====================================================================
__device__ __forceinline__ void ldsm4(uint32_t& r0, uint32_t& r1, uint32_t& r2,
                                      uint32_t& r3, uint32_t addr) {
    asm volatile("ldmatrix.sync.aligned.m8n8.x4.shared.b16 {%0,%1,%2,%3}, [%4];"
                 : "=r"(r0), "=r"(r1), "=r"(r2), "=r"(r3) : "r"(addr));
}
__device__ __forceinline__ void mma16816(float* c, uint32_t a0, uint32_t a1,
                                         uint32_t a2, uint32_t a3,
                                         uint32_t b0, uint32_t b1) {
    asm volatile(
        "mma.sync.aligned.m16n8k16.row.col.f32.bf16.bf16.f32 "
        "{%0,%1,%2,%3}, {%4,%5,%6,%7}, {%8,%9}, {%0,%1,%2,%3};"
        : "+f"(c[0]), "+f"(c[1]), "+f"(c[2]), "+f"(c[3])
        : "r"(a0), "r"(a1), "r"(a2), "r"(a3), "r"(b0), "r"(b1));
}

// =====================================================================
// k1: persistent banded bf16 mma.sync Gram. Fused prep + zero-spin.
// CTA 0 publishes slot tables for k3 (visible via kernel ordering).
// =====================================================================
__global__ void __launch_bounds__(K1_THREADS, 2)
k1_gram(const float* __restrict__ features, const int* __restrict__ labels) {
    extern __shared__ char smem[];
    __shared__ size_t s_roff[B];
    __shared__ int s_slot2s[B];
    __shared__ int s_sl[B], s_ccount[NC], s_cstart[NC + 1];
    __shared__ int s_b0[8];
    __shared__ int s_nt;

    const int tid  = threadIdx.x;
    const int wid  = tid >> 5;
    const int lane = tid & 31;

    // ---- per-CTA prep from labels ----
    prep_slots(labels, tid, s_sl, s_ccount, s_cstart, s_slot2s);
    __syncthreads();
    if (tid < B) s_roff[tid] = (size_t)s_slot2s[tid] * D4;
    if (tid == 0) prep_bands(s_cstart, s_b0, &s_nt);

    // ---- CTA 0 publishes tables for k3 ----
    if (blockIdx.x == 0) {
        if (tid < B) {
            int samp = s_slot2s[tid];
            g_members[tid] = samp;
            int my = s_sl[samp];
            g_cs[tid] = s_cstart[my];
            g_ce[tid] = s_cstart[my + 1];
        }
        if (tid < NC + 1) g_start[tid] = s_cstart[tid];
    }

    // ---- zero own slice of g_pd, then grid arrive/spin (monotonic gen) ----
    {
        const int base = blockIdx.x * 56;
        for (int i = tid; i < 56; i += K1_THREADS) {
            int idx = base + i;
            if (idx < B * B) g_pd[idx] = 0.0f;
        }
        __threadfence();
        __syncthreads();
        if (tid == 0) {
            unsigned int gen = atomicAdd(&g_zero_ctr, 1u) / NCTA2;
            unsigned int target = (gen + 1u) * NCTA2;
            while (atomicAdd(&g_zero_ctr, 0u) < target) { }
        }
        __syncthreads();
        __threadfence();
    }

    const float4* F4 = (const float4*)features;
    const bool wide = (s_nt == 4);
    const int nseg  = wide ? 2 : 1;

    // ---- mma mapping: warp = (strip, band half) ----
    const int strip = wid >> 1;
    const int half  = wid & 1;
    const int m0    = strip * 16;
    const int wbase = s_b0[strip] + half * (wide ? 64 : 32);

    const int a_row    = m0 + (lane & 7) + ((lane >> 3) & 1) * 8;
    const int a_col8   = (lane >> 4) * 8;
    const int b_rowoff = (lane & 7) + ((lane >> 4) & 1) * 8;
    const int b_col8   = ((lane >> 3) & 1) * 8;

    const int gid = lane >> 2;
    const int tig = lane & 3;
    const int r0 = m0 + gid, r1 = m0 + gid + 8;

    float acc[2][8];
    #pragma unroll
    for (int t = 0; t < 2; ++t)
        #pragma unroll
        for (int q = 0; q < 8; ++q) acc[t][q] = 0.0f;

    auto flush = [&](int base_n) {
        #pragma unroll
        for (int nt = 0; nt < 2; ++nt) {
            const int base = base_n + nt * 16;
            const int cA = base + tig * 2;
            const int cC = base + 8 + tig * 2;
            atomicAdd(&g_pd[r0 * B + cA],     acc[nt][0]);
            atomicAdd(&g_pd[r0 * B + cA + 1], acc[nt][1]);
            atomicAdd(&g_pd[r1 * B + cA],     acc[nt][2]);
            atomicAdd(&g_pd[r1 * B + cA + 1], acc[nt][3]);
            atomicAdd(&g_pd[r0 * B + cC],     acc[nt][4]);
            atomicAdd(&g_pd[r0 * B + cC + 1], acc[nt][5]);
            atomicAdd(&g_pd[r1 * B + cC],     acc[nt][6]);
            atomicAdd(&g_pd[r1 * B + cC + 1], acc[nt][7]);
        }
    };

    // ---- preload first chunk (8 rows/warp, float4 col = lane) ----
    float4 buf[8];
    {
        const size_t base4 = (size_t)blockIdx.x * (KT / 4) + lane;
        #pragma unroll
        for (int k = 0; k < 8; ++k)
            buf[k] = F4[s_roff[wid + k * 16] + base4];
    }

    int it = 0;
    for (int c = blockIdx.x; c < NCHUNK; c += NCTA2, ++it) {
        char* tilep = smem + ((it & 1) ? TILE1 : TILE0);
        const uint32_t tile_sh = (uint32_t)__cvta_generic_to_shared(tilep);

        // convert current buf -> STS bf16 tile
        #pragma unroll
        for (int k = 0; k < 8; ++k) {
            const int row = wid + k * 16;
            __nv_bfloat162 h0 = __float22bfloat162_rn(make_float2(buf[k].x, buf[k].y));
            __nv_bfloat162 h1 = __float22bfloat162_rn(make_float2(buf[k].z, buf[k].w));
            uint2 v;
            v.x = *(uint32_t*)&h0;
            v.y = *(uint32_t*)&h1;
            *(uint2*)(tilep + row * (TP * 2) + lane * 8) = v;
        }

        // issue NEXT chunk's LDGs (latency hidden under HMMA)
        {
            const int cn = c + NCTA2;
            if (cn < NCHUNK) {
                const size_t base4 = (size_t)cn * (KT / 4) + lane;
                #pragma unroll
                for (int k = 0; k < 8; ++k)
                    buf[k] = F4[s_roff[wid + k * 16] + base4];
            }
        }

        __syncthreads();

        // banded HMMA (1 segment) / wide fallback (2 segments)
        for (int seg = 0; seg < nseg; ++seg) {
            const int seg_base = wbase + seg * 32;
            #pragma unroll
            for (int ks = 0; ks < 8; ++ks) {
                const int k0c = ks * 16;
                uint32_t a0, a1, a2, a3;
                ldsm4(a0, a1, a2, a3,
                      tile_sh + (uint32_t)(a_row * TP + k0c + a_col8) * 2);
                #pragma unroll
                for (int nt = 0; nt < 2; ++nt) {
                    const int n0 = seg_base + nt * 16;
                    uint32_t b0, b1, b2, b3;
                    ldsm4(b0, b1, b2, b3,
                          tile_sh + (uint32_t)((n0 + b_rowoff) * TP + k0c + b_col8) * 2);
                    mma16816(&acc[nt][0], a0, a1, a2, a3, b0, b1);
                    mma16816(&acc[nt][4], a0, a1, a2, a3, b2, b3);
                }
            }
            if (wide) {
                flush(seg_base);
                #pragma unroll
                for (int t = 0; t < 2; ++t)
                    #pragma unroll
                    for (int q = 0; q < 8; ++q) acc[t][q] = 0.0f;
            }
        }
    }

    if (!wide) flush(wbase);
}

// =====================================================================
// k3: weights (from published tables + L2-resident g_pd) + scatter-sum
// =====================================================================
#define PF 8
__global__ void __launch_bounds__(256) k3_scatter(const float* __restrict__ features,
                                                  float* __restrict__ out) {
    __shared__ float sw[B];
    __shared__ float sdiag[B];
    __shared__ float ssum;
    __shared__ int   sm[B];
    __shared__ int   sst[NC + 1];
    int t = threadIdx.x;
    if (t < B) {
        sm[t] = g_members[t];
        sdiag[t] = g_pd[t * B + t];
    }
    if (t < NC + 1) sst[t] = g_start[t];
    __syncthreads();

    if (t < B) {
        int st = g_cs[t], en = g_ce[t];
        float dsum = 0.0f;
        for (int b = st; b < en; ++b) {
            if (b == t) continue;
            float d2 = sdiag[t] + sdiag[b] - 2.0f * g_pd[t * B + b];
            dsum += (d2 > 0.0f) ? sqrtf(d2) : 0.0f;
        }
        sw[t] = 1.0f / (sqrtf(dsum * dsum + 25.0f) + 1e-12f);
    }
    __syncthreads();
    if (t == 0) {
        float S = 0.0f;
        for (int i = 0; i < B; ++i) S += sw[i];
        ssum = S + 1e-12f;
    }
    __syncthreads();
    if (t < B) sw[t] = sw[t] / ssum;
    __syncthreads();

    // weighted scatter-sum, rolling slot pass, PF-deep prefetch
    const size_t t4 = (size_t)blockIdx.x * 256 + t;
    const float4* F4 = (const float4*)features;
    float4* O4 = (float4*)out;

    float4 buf[PF];
    #pragma unroll
    for (int k = 0; k < PF; ++k)
        buf[k] = F4[(size_t)sm[k] * D4 + t4];

    int c = 0;
    int nb = sst[1];
    float4 acc = make_float4(0.f, 0.f, 0.f, 0.f);

    for (int s0 = 0; s0 < B; s0 += PF) {
        #pragma unroll
        for (int k = 0; k < PF; ++k) {
            int s = s0 + k;
            while (s == nb && c < NC) {
                O4[(size_t)c * D4 + t4] = acc;
                acc = make_float4(0.f, 0.f, 0.f, 0.f);
                ++c;
                nb = sst[c + 1];
            }
            float4 v = buf[k];
            float w = sw[s];
            acc.x += w * v.x; acc.y += w * v.y;
            acc.z += w * v.z; acc.w += w * v.w;
            int sp = s + PF;
            if (sp < B) buf[k] = F4[(size_t)sm[sp] * D4 + t4];
        }
    }
    while (c < NC) {
        O4[(size_t)c * D4 + t4] = acc;
        acc = make_float4(0.f, 0.f, 0.f, 0.f);
        ++c;
    }
}

// =====================================================================
extern "C" void kernel_launch(void* const* d_in, const int* in_sizes, int n_in,
                              void* d_out, int out_size) {
    const float* features;
    const int*   labels;
    if (in_sizes[0] == B) {
        labels   = (const int*)d_in[0];
        features = (const float*)d_in[1];
    } else {
        features = (const float*)d_in[0];
        labels   = (const int*)d_in[1];
    }
    float* out = (float*)d_out;

    (void)cudaFuncSetAttribute((const void*)k1_gram,
                               cudaFuncAttributeMaxDynamicSharedMemorySize,
                               SMEM_DYN);

    k1_gram<<<NCTA2, K1_THREADS, SMEM_DYN>>>(features, labels);
    k3_scatter<<<D4 / 256, 256>>>(features, out);
}